// round 16
// baseline (speedup 1.0000x reference)
#include <cuda_runtime.h>
#include <cuda_fp16.h>
#include <math.h>
#include <stdint.h>

// ---------------------------------------------------------------------------
// E64AdditiveHCell — R15 base + MUFU-free sigmoid in recurrence
//  1) fused prepass: X, Wa, Wx -> fp16
//  2) dual fp16 GEMM (m16n8k16, fp32 accum), BM=128 BN=64, 2 CTAs/SM
//  3) recurrence: 1 chain/thread, interleaved 32-deep prefetch, 24-cyc chain,
//     out-sigmoid via degree-7 odd polynomial (|h|<=1 provable: h is a convex
//     combination of h0=0 and tanh values) -> only 1 MUFU/step (the tanh)
// ---------------------------------------------------------------------------

#define BM 128
#define BN 64
#define NKS 16                 // K chunks: 1024 / 64
#define HST_B 144              // smem row stride in bytes
#define A_BYTES (128 * HST_B)
#define B_BYTES (64 * HST_B)
#define STG_BYTES (A_BYTES + 2 * B_BYTES)   // 36864
#define A_OFF  0
#define BA_OFF A_BYTES
#define BW_OFF (A_BYTES + B_BYTES)

#define MAX_T 2048
#define MAX_BD 8192
#define MAX_M 16384
#define MAX_K 1024
__device__ __half2 g_aw[(size_t)MAX_T * MAX_BD];    // {alpha, wx} fp16
__device__ __half  g_x [(size_t)MAX_M * MAX_K];
__device__ __half  g_wa[(size_t)MAX_K * MAX_K];
__device__ __half  g_wx[(size_t)MAX_K * MAX_K];

// ---------------- helpers ----------------
__device__ __forceinline__ float ex2f(float x) {
    float r; asm("ex2.approx.ftz.f32 %0, %1;" : "=f"(r) : "f"(x)); return r;
}
__device__ __forceinline__ float rcpf(float x) {
    float r; asm("rcp.approx.ftz.f32 %0, %1;" : "=f"(r) : "f"(x)); return r;
}
__device__ __forceinline__ float tanhx(float x) {
    float r; asm("tanh.approx.f32 %0, %1;" : "=f"(r) : "f"(x)); return r;
}
__device__ __forceinline__ float fast_sigmoid(float x) {
    return rcpf(1.0f + ex2f(-1.4426950408889634f * x));
}
__device__ __forceinline__ void mma_f16(float c[4], const uint32_t a[4],
                                        uint32_t b0, uint32_t b1) {
    asm volatile(
        "mma.sync.aligned.m16n8k16.row.col.f32.f16.f16.f32 "
        "{%0,%1,%2,%3},{%4,%5,%6,%7},{%8,%9},{%0,%1,%2,%3};"
        : "+f"(c[0]), "+f"(c[1]), "+f"(c[2]), "+f"(c[3])
        : "r"(a[0]), "r"(a[1]), "r"(a[2]), "r"(a[3]), "r"(b0), "r"(b1));
}
__device__ __forceinline__ void ldsm4(uint32_t r[4], uint32_t addr) {
    asm volatile("ldmatrix.sync.aligned.m8n8.x4.shared.b16 {%0,%1,%2,%3}, [%4];"
        : "=r"(r[0]), "=r"(r[1]), "=r"(r[2]), "=r"(r[3]) : "r"(addr));
}
__device__ __forceinline__ void cp16(uint32_t dst, const void* src) {
    asm volatile("cp.async.cg.shared.global [%0], [%1], 16;" :: "r"(dst), "l"(src));
}
__device__ __forceinline__ void cp_commit() { asm volatile("cp.async.commit_group;"); }
__device__ __forceinline__ void cp_wait0()  { asm volatile("cp.async.wait_group 0;" ::: "memory"); }
__device__ __forceinline__ void cp_wait1()  { asm volatile("cp.async.wait_group 1;" ::: "memory"); }

// streaming-hint accessors
__device__ __forceinline__ uint32_t ldcs_u32(const uint32_t* p) {
    uint32_t r; asm volatile("ld.global.cs.b32 %0, [%1];" : "=r"(r) : "l"(p)); return r;
}
__device__ __forceinline__ void stcs_f32(float* p, float v) {
    asm volatile("st.global.cs.f32 [%0], %1;" :: "l"(p), "f"(v));
}

// ---------------------------------------------------------------------------
// 1) fused fp32 -> fp16 prepass
// ---------------------------------------------------------------------------
__global__ void __launch_bounds__(256)
f2h_all(const float* __restrict__ x, const float* __restrict__ wa,
        const float* __restrict__ wx,
        __half* __restrict__ gx, __half* __restrict__ gwa,
        __half* __restrict__ gwx, int nx4, int nw4)
{
    int i = blockIdx.x * blockDim.x + threadIdx.x;
    const float* src; __half* dst; int j;
    if (i < nx4)                { src = x;  dst = gx;  j = i; }
    else if (i < nx4 + nw4)     { src = wa; dst = gwa; j = i - nx4; }
    else if (i < nx4 + 2 * nw4) { src = wx; dst = gwx; j = i - nx4 - nw4; }
    else return;
    float4 v = ((const float4*)src)[j];
    __half2 h0 = __floats2half2_rn(v.x, v.y);
    __half2 h1 = __floats2half2_rn(v.z, v.w);
    uint2 o;
    o.x = *(uint32_t*)&h0;
    o.y = *(uint32_t*)&h1;
    ((uint2*)dst)[j] = o;
}

// ---------------------------------------------------------------------------
// 2) fused dual fp16 GEMM: 256 threads, warps 4(m) x 2(n), warp tile 32x32/W,
//    2 CTAs per SM, single launch.  (identical to R10/R15)
// ---------------------------------------------------------------------------
extern __shared__ __align__(128) char smem_raw[];

__global__ void __launch_bounds__(256, 2)
gemm2_f16(const __half* __restrict__ X,  const __half* __restrict__ Wa,
          const __half* __restrict__ Wx, const float* __restrict__ ba,
          const float* __restrict__ bb)
{
    __shared__ float s_ba[BN], s_bb[BN];

    const int t    = threadIdx.x;
    const int lane = t & 31;
    const int warp = t >> 5;
    const int g    = lane >> 2;
    const int tid4 = lane & 3;
    const int wm   = warp >> 1;     // 0..3
    const int wn   = warp & 1;      // 0..1
    const int m0   = blockIdx.y * BM;
    const int n0   = blockIdx.x * BN;

    uint32_t dyn_u32 = (uint32_t)__cvta_generic_to_shared(smem_raw);

    if (t < BN) { s_ba[t] = ba[n0 + t]; s_bb[t] = bb[n0 + t]; }

    float accA[2][4][4];
    float accW[2][4][4];
#pragma unroll
    for (int mi = 0; mi < 2; mi++)
#pragma unroll
        for (int ni = 0; ni < 4; ni++)
#pragma unroll
            for (int r = 0; r < 4; r++) { accA[mi][ni][r] = 0.f; accW[mi][ni][r] = 0.f; }

    uint32_t aBase[2];
#pragma unroll
    for (int mi = 0; mi < 2; mi++) {
        int row = wm * 32 + mi * 16 + (lane & 15);
        aBase[mi] = dyn_u32 + A_OFF + (uint32_t)(row * HST_B) + ((lane >> 4) << 4);
    }
    uint32_t bBaseA[2], bBaseW[2];
#pragma unroll
    for (int p = 0; p < 2; p++) {
        int row = wn * 32 + p * 16 + ((lane >> 4) << 3) + (lane & 7);
        uint32_t off = (uint32_t)(row * HST_B) + (((lane >> 3) & 1) << 4);
        bBaseA[p] = dyn_u32 + BA_OFF + off;
        bBaseW[p] = dyn_u32 + BW_OFF + off;
    }

    const __half* Xb  = X  + (size_t)m0 * MAX_K;
    const __half* Wab = Wa + (size_t)n0 * MAX_K;
    const __half* Wxb = Wx + (size_t)n0 * MAX_K;

    auto issue = [&](int ks, int b) {
        uint32_t dbase = dyn_u32 + (uint32_t)b * STG_BYTES;
        const size_t kof = (size_t)ks * 64;    // halves
#pragma unroll
        for (int i = 0; i < 4; i++) {          // A: 1024 16B-chunks
            int ch  = i * 256 + t;
            int row = ch >> 3, q = ch & 7;
            uint32_t so = (uint32_t)(row * HST_B + q * 16);
            cp16(dbase + A_OFF + so, Xb + (size_t)row * MAX_K + kof + (size_t)q * 8);
        }
#pragma unroll
        for (int i = 0; i < 2; i++) {          // B_A and B_W: 512 each
            int ch  = i * 256 + t;
            int row = ch >> 3, q = ch & 7;
            uint32_t so = (uint32_t)(row * HST_B + q * 16);
            size_t go = (size_t)row * MAX_K + kof + (size_t)q * 8;
            cp16(dbase + BA_OFF + so, Wab + go);
            cp16(dbase + BW_OFF + so, Wxb + go);
        }
        cp_commit();
    };

    issue(0, 0); issue(1, 1);

    for (int c = 0; c < NKS; c++) {
        const uint32_t stgofs = (uint32_t)(c % 3) * STG_BYTES;
        if (c < NKS - 1) cp_wait1(); else cp_wait0();
        __syncthreads();
        if (c + 2 < NKS) issue(c + 2, (c + 2) % 3);

#pragma unroll
        for (int kk = 0; kk < 4; kk++) {
            const uint32_t kb = stgofs + kk * 32;
            uint32_t af[2][4];
#pragma unroll
            for (int mi = 0; mi < 2; mi++) ldsm4(af[mi], aBase[mi] + kb);
            uint32_t bfA[2][4], bfW[2][4];
#pragma unroll
            for (int p = 0; p < 2; p++) {
                ldsm4(bfA[p], bBaseA[p] + kb);
                ldsm4(bfW[p], bBaseW[p] + kb);
            }
#pragma unroll
            for (int mi = 0; mi < 2; mi++)
#pragma unroll
                for (int ni = 0; ni < 4; ni++) {
                    const int p = ni >> 1, s = (ni & 1) * 2;
                    mma_f16(accA[mi][ni], af[mi], bfA[p][s], bfA[p][s + 1]);
                    mma_f16(accW[mi][ni], af[mi], bfW[p][s], bfW[p][s + 1]);
                }
        }
    }
    __syncthreads();

    // Epilogue: bias + fast sigmoid(alpha), half2 {alpha, wx} stores
#pragma unroll
    for (int ni = 0; ni < 4; ni++) {
        const int col0 = n0 + wn * 32 + ni * 8 + 2 * tid4;
        const float ba0 = s_ba[col0 - n0], ba1 = s_ba[col0 - n0 + 1];
        const float bb0 = s_bb[col0 - n0], bb1 = s_bb[col0 - n0 + 1];
#pragma unroll
        for (int mi = 0; mi < 2; mi++) {
            const int row0 = m0 + wm * 32 + mi * 16 + g;
            {
                __half2 p0 = __floats2half2_rn(
                    fast_sigmoid(accA[mi][ni][0] + ba0), accW[mi][ni][0] + bb0);
                __half2 p1 = __floats2half2_rn(
                    fast_sigmoid(accA[mi][ni][1] + ba1), accW[mi][ni][1] + bb1);
                uint2 v = { *(uint32_t*)&p0, *(uint32_t*)&p1 };
                *(uint2*)&g_aw[(size_t)row0 * MAX_K + col0] = v;
            }
            {
                __half2 p0 = __floats2half2_rn(
                    fast_sigmoid(accA[mi][ni][2] + ba0), accW[mi][ni][2] + bb0);
                __half2 p1 = __floats2half2_rn(
                    fast_sigmoid(accA[mi][ni][3] + ba1), accW[mi][ni][3] + bb1);
                uint2 v = { *(uint32_t*)&p0, *(uint32_t*)&p1 };
                *(uint2*)&g_aw[(size_t)(row0 + 8) * MAX_K + col0] = v;
            }
        }
    }
}

// ---------------------------------------------------------------------------
// 3) Recurrence: 1 chain/thread, interleaved prefetch (__ldcs), 24-cyc chain,
//    polynomial sigmoid for out (|h| <= 1 guaranteed), streaming stores.
//    sigma(x) ~= 0.5 + x(c1 + x^2(c3 + x^2(c5 + x^2 c7))), |err| <= 2.2e-5.
// ---------------------------------------------------------------------------
__device__ __forceinline__ float poly_sigmoid_unit(float x) {
    // Taylor (odd) coefficients of sigmoid about 0; valid for |x| <= 1
    const float c1 =  0.25f;
    const float c3 = -2.0833333333e-2f;
    const float c5 =  2.0833333333e-3f;
    const float c7 = -2.1081349206e-4f;
    float u = x * x;
    float p = fmaf(u, c7, c5);
    p = fmaf(u, p, c3);
    p = fmaf(u, p, c1);
    return fmaf(x, p, 0.5f);
}

__global__ void __launch_bounds__(64)
recur_kernel(const float* __restrict__ h0,
             float* __restrict__ out,   // [T, BD]
             float* __restrict__ hout,  // [T+1, BD]
             int T, int BD)
{
    const int idx = blockIdx.x * blockDim.x + threadIdx.x;
    if (idx >= BD) return;

    float h = h0[idx];
    hout[idx] = h;

    const uint32_t* __restrict__ aw = (const uint32_t*)g_aw + idx;
    float* __restrict__ hw = hout + BD + idx;
    float* __restrict__ ow = out + idx;

    uint32_t buf0[32], buf1[32];
#pragma unroll
    for (int u = 0; u < 32; u++) buf0[u] = ldcs_u32(aw + (size_t)u * BD);

    for (int tt = 0; tt < T; tt += 64) {
        const bool more = (tt + 64 < T);
#pragma unroll
        for (int u = 0; u < 32; u++) {
            // interleaved prefetch for the next half-group
            buf1[u] = ldcs_u32(aw + (size_t)(tt + 32 + u) * BD);
            float2 f = __half22float2(*(__half2*)&buf0[u]);
            const float a = f.x, w = f.y;
            const float p = 1.0f - a;          // off-path
            float v = tanhx(h + w);            // FADD + MUFU (only MUFU/step)
            float t1 = a * h;                  // in tanh shadow
            h = fmaf(p, v, t1);                // single post-tanh FMA
            float sg = poly_sigmoid_unit(h);   // FMA pipe, off MUFU port
            size_t o = (size_t)(tt + u) * BD;
            stcs_f32(ow + o, h * h * sg);
            stcs_f32(hw + o, h);
        }
#pragma unroll
        for (int u = 0; u < 32; u++) {
            if (more) buf0[u] = ldcs_u32(aw + (size_t)(tt + 64 + u) * BD);
            float2 f = __half22float2(*(__half2*)&buf1[u]);
            const float a = f.x, w = f.y;
            const float p = 1.0f - a;
            float v = tanhx(h + w);
            float t1 = a * h;
            h = fmaf(p, v, t1);
            float sg = poly_sigmoid_unit(h);
            size_t o = (size_t)(tt + 32 + u) * BD;
            stcs_f32(ow + o, h * h * sg);
            stcs_f32(hw + o, h);
        }
    }
}

// ---------------------------------------------------------------------------
extern "C" void kernel_launch(void* const* d_in, const int* in_sizes, int n_in,
                              void* d_out, int out_size)
{
    const float* x  = (const float*)d_in[0];
    const float* h0 = (const float*)d_in[1];
    const float* Wa = (const float*)d_in[2];
    const float* ba = (const float*)d_in[3];
    const float* Wx = (const float*)d_in[4];
    const float* bb = (const float*)d_in[5];

    const int BD = in_sizes[1];               // 8192
    const int D  = in_sizes[3];               // 1024
    const int M  = in_sizes[0] / D;           // 16384
    const int T  = in_sizes[0] / BD;          // 2048

    float* out  = (float*)d_out;
    float* hout = (float*)d_out + (size_t)T * BD;

    __half* gx;  cudaGetSymbolAddress((void**)&gx,  g_x);
    __half* gwa; cudaGetSymbolAddress((void**)&gwa, g_wa);
    __half* gwx; cudaGetSymbolAddress((void**)&gwx, g_wx);

    // 1) fused fp16 prepass
    {
        int nx4 = (M * D) / 4;
        int nw4 = (D * D) / 4;
        int tot = nx4 + 2 * nw4;
        f2h_all<<<(tot + 255) / 256, 256>>>(x, Wa, Wx, gx, gwa, gwx, nx4, nw4);
    }

    // 2) dual fp16 GEMM, 2 CTAs/SM, single launch
    const int SMEM_BYTES = 3 * STG_BYTES;           // 110592
    cudaFuncSetAttribute(gemm2_f16, cudaFuncAttributeMaxDynamicSharedMemorySize, SMEM_BYTES);
    dim3 grid(D / BN, M / BM);   // (16, 128) = 2048 CTAs
    gemm2_f16<<<grid, 256, SMEM_BYTES>>>(gx, gwa, gwx, ba, bb);

    // 3) recurrence + fused out
    recur_kernel<<<(BD + 63) / 64, 64>>>(h0, out, hout, T, BD);
}

// round 17
// speedup vs baseline: 1.0642x; 1.0642x over previous
#include <cuda_runtime.h>
#include <cuda_fp16.h>
#include <math.h>
#include <stdint.h>

// ---------------------------------------------------------------------------
// E64AdditiveHCell — R15 base + poly sigmoid ONLY (block prefetch retained)
//  1) fused prepass: X, Wa, Wx -> fp16
//  2) dual fp16 GEMM (m16n8k16, fp32 accum), BM=128 BN=64, 2 CTAs/SM
//  3) recurrence: 1 chain/thread, BLOCK 32-deep prefetch (as R15),
//     24-cyc chain, out-sigmoid via degree-7 odd polynomial (|h|<=1),
//     streaming cache hints
// ---------------------------------------------------------------------------

#define BM 128
#define BN 64
#define NKS 16                 // K chunks: 1024 / 64
#define HST_B 144              // smem row stride in bytes
#define A_BYTES (128 * HST_B)
#define B_BYTES (64 * HST_B)
#define STG_BYTES (A_BYTES + 2 * B_BYTES)   // 36864
#define A_OFF  0
#define BA_OFF A_BYTES
#define BW_OFF (A_BYTES + B_BYTES)

#define MAX_T 2048
#define MAX_BD 8192
#define MAX_M 16384
#define MAX_K 1024
__device__ __half2 g_aw[(size_t)MAX_T * MAX_BD];    // {alpha, wx} fp16
__device__ __half  g_x [(size_t)MAX_M * MAX_K];
__device__ __half  g_wa[(size_t)MAX_K * MAX_K];
__device__ __half  g_wx[(size_t)MAX_K * MAX_K];

// ---------------- helpers ----------------
__device__ __forceinline__ float ex2f(float x) {
    float r; asm("ex2.approx.ftz.f32 %0, %1;" : "=f"(r) : "f"(x)); return r;
}
__device__ __forceinline__ float rcpf(float x) {
    float r; asm("rcp.approx.ftz.f32 %0, %1;" : "=f"(r) : "f"(x)); return r;
}
__device__ __forceinline__ float tanhx(float x) {
    float r; asm("tanh.approx.f32 %0, %1;" : "=f"(r) : "f"(x)); return r;
}
__device__ __forceinline__ float fast_sigmoid(float x) {
    return rcpf(1.0f + ex2f(-1.4426950408889634f * x));
}
__device__ __forceinline__ void mma_f16(float c[4], const uint32_t a[4],
                                        uint32_t b0, uint32_t b1) {
    asm volatile(
        "mma.sync.aligned.m16n8k16.row.col.f32.f16.f16.f32 "
        "{%0,%1,%2,%3},{%4,%5,%6,%7},{%8,%9},{%0,%1,%2,%3};"
        : "+f"(c[0]), "+f"(c[1]), "+f"(c[2]), "+f"(c[3])
        : "r"(a[0]), "r"(a[1]), "r"(a[2]), "r"(a[3]), "r"(b0), "r"(b1));
}
__device__ __forceinline__ void ldsm4(uint32_t r[4], uint32_t addr) {
    asm volatile("ldmatrix.sync.aligned.m8n8.x4.shared.b16 {%0,%1,%2,%3}, [%4];"
        : "=r"(r[0]), "=r"(r[1]), "=r"(r[2]), "=r"(r[3]) : "r"(addr));
}
__device__ __forceinline__ void cp16(uint32_t dst, const void* src) {
    asm volatile("cp.async.cg.shared.global [%0], [%1], 16;" :: "r"(dst), "l"(src));
}
__device__ __forceinline__ void cp_commit() { asm volatile("cp.async.commit_group;"); }
__device__ __forceinline__ void cp_wait0()  { asm volatile("cp.async.wait_group 0;" ::: "memory"); }
__device__ __forceinline__ void cp_wait1()  { asm volatile("cp.async.wait_group 1;" ::: "memory"); }

// streaming-hint accessors
__device__ __forceinline__ uint32_t ldcs_u32(const uint32_t* p) {
    uint32_t r; asm volatile("ld.global.cs.b32 %0, [%1];" : "=r"(r) : "l"(p)); return r;
}
__device__ __forceinline__ void stcs_f32(float* p, float v) {
    asm volatile("st.global.cs.f32 [%0], %1;" :: "l"(p), "f"(v));
}

// ---------------------------------------------------------------------------
// 1) fused fp32 -> fp16 prepass
// ---------------------------------------------------------------------------
__global__ void __launch_bounds__(256)
f2h_all(const float* __restrict__ x, const float* __restrict__ wa,
        const float* __restrict__ wx,
        __half* __restrict__ gx, __half* __restrict__ gwa,
        __half* __restrict__ gwx, int nx4, int nw4)
{
    int i = blockIdx.x * blockDim.x + threadIdx.x;
    const float* src; __half* dst; int j;
    if (i < nx4)                { src = x;  dst = gx;  j = i; }
    else if (i < nx4 + nw4)     { src = wa; dst = gwa; j = i - nx4; }
    else if (i < nx4 + 2 * nw4) { src = wx; dst = gwx; j = i - nx4 - nw4; }
    else return;
    float4 v = ((const float4*)src)[j];
    __half2 h0 = __floats2half2_rn(v.x, v.y);
    __half2 h1 = __floats2half2_rn(v.z, v.w);
    uint2 o;
    o.x = *(uint32_t*)&h0;
    o.y = *(uint32_t*)&h1;
    ((uint2*)dst)[j] = o;
}

// ---------------------------------------------------------------------------
// 2) fused dual fp16 GEMM: 256 threads, warps 4(m) x 2(n), warp tile 32x32/W,
//    2 CTAs per SM, single launch.  (identical to R10/R15)
// ---------------------------------------------------------------------------
extern __shared__ __align__(128) char smem_raw[];

__global__ void __launch_bounds__(256, 2)
gemm2_f16(const __half* __restrict__ X,  const __half* __restrict__ Wa,
          const __half* __restrict__ Wx, const float* __restrict__ ba,
          const float* __restrict__ bb)
{
    __shared__ float s_ba[BN], s_bb[BN];

    const int t    = threadIdx.x;
    const int lane = t & 31;
    const int warp = t >> 5;
    const int g    = lane >> 2;
    const int tid4 = lane & 3;
    const int wm   = warp >> 1;     // 0..3
    const int wn   = warp & 1;      // 0..1
    const int m0   = blockIdx.y * BM;
    const int n0   = blockIdx.x * BN;

    uint32_t dyn_u32 = (uint32_t)__cvta_generic_to_shared(smem_raw);

    if (t < BN) { s_ba[t] = ba[n0 + t]; s_bb[t] = bb[n0 + t]; }

    float accA[2][4][4];
    float accW[2][4][4];
#pragma unroll
    for (int mi = 0; mi < 2; mi++)
#pragma unroll
        for (int ni = 0; ni < 4; ni++)
#pragma unroll
            for (int r = 0; r < 4; r++) { accA[mi][ni][r] = 0.f; accW[mi][ni][r] = 0.f; }

    uint32_t aBase[2];
#pragma unroll
    for (int mi = 0; mi < 2; mi++) {
        int row = wm * 32 + mi * 16 + (lane & 15);
        aBase[mi] = dyn_u32 + A_OFF + (uint32_t)(row * HST_B) + ((lane >> 4) << 4);
    }
    uint32_t bBaseA[2], bBaseW[2];
#pragma unroll
    for (int p = 0; p < 2; p++) {
        int row = wn * 32 + p * 16 + ((lane >> 4) << 3) + (lane & 7);
        uint32_t off = (uint32_t)(row * HST_B) + (((lane >> 3) & 1) << 4);
        bBaseA[p] = dyn_u32 + BA_OFF + off;
        bBaseW[p] = dyn_u32 + BW_OFF + off;
    }

    const __half* Xb  = X  + (size_t)m0 * MAX_K;
    const __half* Wab = Wa + (size_t)n0 * MAX_K;
    const __half* Wxb = Wx + (size_t)n0 * MAX_K;

    auto issue = [&](int ks, int b) {
        uint32_t dbase = dyn_u32 + (uint32_t)b * STG_BYTES;
        const size_t kof = (size_t)ks * 64;    // halves
#pragma unroll
        for (int i = 0; i < 4; i++) {          // A: 1024 16B-chunks
            int ch  = i * 256 + t;
            int row = ch >> 3, q = ch & 7;
            uint32_t so = (uint32_t)(row * HST_B + q * 16);
            cp16(dbase + A_OFF + so, Xb + (size_t)row * MAX_K + kof + (size_t)q * 8);
        }
#pragma unroll
        for (int i = 0; i < 2; i++) {          // B_A and B_W: 512 each
            int ch  = i * 256 + t;
            int row = ch >> 3, q = ch & 7;
            uint32_t so = (uint32_t)(row * HST_B + q * 16);
            size_t go = (size_t)row * MAX_K + kof + (size_t)q * 8;
            cp16(dbase + BA_OFF + so, Wab + go);
            cp16(dbase + BW_OFF + so, Wxb + go);
        }
        cp_commit();
    };

    issue(0, 0); issue(1, 1);

    for (int c = 0; c < NKS; c++) {
        const uint32_t stgofs = (uint32_t)(c % 3) * STG_BYTES;
        if (c < NKS - 1) cp_wait1(); else cp_wait0();
        __syncthreads();
        if (c + 2 < NKS) issue(c + 2, (c + 2) % 3);

#pragma unroll
        for (int kk = 0; kk < 4; kk++) {
            const uint32_t kb = stgofs + kk * 32;
            uint32_t af[2][4];
#pragma unroll
            for (int mi = 0; mi < 2; mi++) ldsm4(af[mi], aBase[mi] + kb);
            uint32_t bfA[2][4], bfW[2][4];
#pragma unroll
            for (int p = 0; p < 2; p++) {
                ldsm4(bfA[p], bBaseA[p] + kb);
                ldsm4(bfW[p], bBaseW[p] + kb);
            }
#pragma unroll
            for (int mi = 0; mi < 2; mi++)
#pragma unroll
                for (int ni = 0; ni < 4; ni++) {
                    const int p = ni >> 1, s = (ni & 1) * 2;
                    mma_f16(accA[mi][ni], af[mi], bfA[p][s], bfA[p][s + 1]);
                    mma_f16(accW[mi][ni], af[mi], bfW[p][s], bfW[p][s + 1]);
                }
        }
    }
    __syncthreads();

    // Epilogue: bias + fast sigmoid(alpha), half2 {alpha, wx} stores
#pragma unroll
    for (int ni = 0; ni < 4; ni++) {
        const int col0 = n0 + wn * 32 + ni * 8 + 2 * tid4;
        const float ba0 = s_ba[col0 - n0], ba1 = s_ba[col0 - n0 + 1];
        const float bb0 = s_bb[col0 - n0], bb1 = s_bb[col0 - n0 + 1];
#pragma unroll
        for (int mi = 0; mi < 2; mi++) {
            const int row0 = m0 + wm * 32 + mi * 16 + g;
            {
                __half2 p0 = __floats2half2_rn(
                    fast_sigmoid(accA[mi][ni][0] + ba0), accW[mi][ni][0] + bb0);
                __half2 p1 = __floats2half2_rn(
                    fast_sigmoid(accA[mi][ni][1] + ba1), accW[mi][ni][1] + bb1);
                uint2 v = { *(uint32_t*)&p0, *(uint32_t*)&p1 };
                *(uint2*)&g_aw[(size_t)row0 * MAX_K + col0] = v;
            }
            {
                __half2 p0 = __floats2half2_rn(
                    fast_sigmoid(accA[mi][ni][2] + ba0), accW[mi][ni][2] + bb0);
                __half2 p1 = __floats2half2_rn(
                    fast_sigmoid(accA[mi][ni][3] + ba1), accW[mi][ni][3] + bb1);
                uint2 v = { *(uint32_t*)&p0, *(uint32_t*)&p1 };
                *(uint2*)&g_aw[(size_t)(row0 + 8) * MAX_K + col0] = v;
            }
        }
    }
}

// ---------------------------------------------------------------------------
// 3) Recurrence: 1 chain/thread, BLOCK 32-deep prefetch (R15 schedule),
//    24-cyc chain, polynomial sigmoid for out (|h| <= 1), streaming stores.
//    sigma(x) ~= 0.5 + x(c1 + u(c3 + u(c5 + u c7))), u = x^2, |err| <= 2.2e-5.
// ---------------------------------------------------------------------------
__device__ __forceinline__ float poly_sigmoid_unit(float x) {
    const float c1 =  0.25f;
    const float c3 = -2.0833333333e-2f;
    const float c5 =  2.0833333333e-3f;
    const float c7 = -2.1081349206e-4f;
    float u = x * x;
    float p = fmaf(u, c7, c5);
    p = fmaf(u, p, c3);
    p = fmaf(u, p, c1);
    return fmaf(x, p, 0.5f);
}

__global__ void __launch_bounds__(64)
recur_kernel(const float* __restrict__ h0,
             float* __restrict__ out,   // [T, BD]
             float* __restrict__ hout,  // [T+1, BD]
             int T, int BD)
{
    const int idx = blockIdx.x * blockDim.x + threadIdx.x;
    if (idx >= BD) return;

    float h = h0[idx];
    hout[idx] = h;

    const uint32_t* __restrict__ aw = (const uint32_t*)g_aw + idx;
    float* __restrict__ hw = hout + BD + idx;
    float* __restrict__ ow = out + idx;

    uint32_t buf0[32], buf1[32];
#pragma unroll
    for (int u = 0; u < 32; u++) buf0[u] = ldcs_u32(aw + (size_t)u * BD);

    for (int tt = 0; tt < T; tt += 64) {
#pragma unroll
        for (int u = 0; u < 32; u++)
            buf1[u] = ldcs_u32(aw + (size_t)(tt + 32 + u) * BD);
#pragma unroll
        for (int u = 0; u < 32; u++) {
            float2 f = __half22float2(*(__half2*)&buf0[u]);
            const float a = f.x, w = f.y;
            const float p = 1.0f - a;          // off-path
            float v = tanhx(h + w);            // FADD + MUFU (only MUFU/step)
            float t1 = a * h;                  // in tanh shadow
            h = fmaf(p, v, t1);                // single post-tanh FMA
            float sg = poly_sigmoid_unit(h);   // FMA pipe, off MUFU port
            size_t o = (size_t)(tt + u) * BD;
            stcs_f32(ow + o, h * h * sg);
            stcs_f32(hw + o, h);
        }
        if (tt + 64 < T) {
#pragma unroll
            for (int u = 0; u < 32; u++)
                buf0[u] = ldcs_u32(aw + (size_t)(tt + 64 + u) * BD);
        }
#pragma unroll
        for (int u = 0; u < 32; u++) {
            float2 f = __half22float2(*(__half2*)&buf1[u]);
            const float a = f.x, w = f.y;
            const float p = 1.0f - a;
            float v = tanhx(h + w);
            float t1 = a * h;
            h = fmaf(p, v, t1);
            float sg = poly_sigmoid_unit(h);
            size_t o = (size_t)(tt + 32 + u) * BD;
            stcs_f32(ow + o, h * h * sg);
            stcs_f32(hw + o, h);
        }
    }
}

// ---------------------------------------------------------------------------
extern "C" void kernel_launch(void* const* d_in, const int* in_sizes, int n_in,
                              void* d_out, int out_size)
{
    const float* x  = (const float*)d_in[0];
    const float* h0 = (const float*)d_in[1];
    const float* Wa = (const float*)d_in[2];
    const float* ba = (const float*)d_in[3];
    const float* Wx = (const float*)d_in[4];
    const float* bb = (const float*)d_in[5];

    const int BD = in_sizes[1];               // 8192
    const int D  = in_sizes[3];               // 1024
    const int M  = in_sizes[0] / D;           // 16384
    const int T  = in_sizes[0] / BD;          // 2048

    float* out  = (float*)d_out;
    float* hout = (float*)d_out + (size_t)T * BD;

    __half* gx;  cudaGetSymbolAddress((void**)&gx,  g_x);
    __half* gwa; cudaGetSymbolAddress((void**)&gwa, g_wa);
    __half* gwx; cudaGetSymbolAddress((void**)&gwx, g_wx);

    // 1) fused fp16 prepass
    {
        int nx4 = (M * D) / 4;
        int nw4 = (D * D) / 4;
        int tot = nx4 + 2 * nw4;
        f2h_all<<<(tot + 255) / 256, 256>>>(x, Wa, Wx, gx, gwa, gwx, nx4, nw4);
    }

    // 2) dual fp16 GEMM, 2 CTAs/SM, single launch
    const int SMEM_BYTES = 3 * STG_BYTES;           // 110592
    cudaFuncSetAttribute(gemm2_f16, cudaFuncAttributeMaxDynamicSharedMemorySize, SMEM_BYTES);
    dim3 grid(D / BN, M / BM);   // (16, 128) = 2048 CTAs
    gemm2_f16<<<grid, 256, SMEM_BYTES>>>(gx, gwa, gwx, ba, bb);

    // 3) recurrence + fused out
    recur_kernel<<<(BD + 63) / 64, 64>>>(h0, out, hout, T, BD);
}